// round 1
// baseline (speedup 1.0000x reference)
#include <cuda_runtime.h>

#define B_ 32
#define C_ 256
#define H_ 32
#define W_ 32
#define K_ 1024
#define N_ 1024   /* hw positions per batch */
#define I_ 256    /* reduction dim (reinterpreted "channel") */
#define ZELEMS (B_*C_*H_*W_)   /* 8388608 */
#define NPOS   (B_*N_)         /* 32768   */

// Scratch (static __device__ — no allocations allowed)
__device__ float  g_zz[B_][I_][N_];   // 32 MB reinterpreted z_p view
__device__ float  g_t[NPOS];          // ||v_n||^2 per (b,n)
__device__ float  g_s[K_];            // ||e_k||^2
__device__ float  g_pmin[NPOS*8];     // per-kblock partial min
__device__ int    g_pidx[NPOS*8];
__device__ int    g_idx[NPOS];
__device__ double g_lacc;             // loss accumulator

__global__ void k_init() { g_lacc = 0.0; }

// zz[b,i,n] = z[b, n&255, i>>3, 4*(i&7)+(n>>8)]  (the reshape-reinterpretation)
__global__ __launch_bounds__(256) void k_transpose(const float* __restrict__ z) {
    __shared__ float tile[64][33];
    int c0 = blockIdx.x * 64;
    int h  = blockIdx.y;
    int b  = blockIdx.z;
    int t  = threadIdx.x;
    for (int e = t; e < 2048; e += 256) {
        int row = e >> 5, w = e & 31;
        tile[row][w] = z[(((b*C_) + c0 + row)*H_ + h)*W_ + w];
    }
    __syncthreads();
    for (int e = t; e < 2048; e += 256) {
        int cc = e & 63, chunk = e >> 6;
        int il = chunk >> 2, q = chunk & 3;       // w = il*4 + q
        g_zz[b][h*8 + il][q*256 + c0 + cc] = tile[cc][il*4 + q];
    }
}

// t_n = sum_i fl(v*v), sequential ascending, separate mul/add rounding (matches zz*zz then sum)
__global__ __launch_bounds__(256) void k_tn() {
    int gn = blockIdx.x*blockDim.x + threadIdx.x;
    if (gn >= NPOS) return;
    int b = gn >> 10, n = gn & 1023;
    float acc = 0.f;
    for (int i = 0; i < I_; ++i) {
        float v = g_zz[b][i][n];
        acc = __fadd_rn(acc, __fmul_rn(v, v));
    }
    g_t[gn] = acc;
}

__global__ __launch_bounds__(256) void k_sk(const float* __restrict__ emb) {
    int k = blockIdx.x*blockDim.x + threadIdx.x;
    if (k >= K_) return;
    float acc = 0.f;
    for (int c = 0; c < C_; ++c) {
        float v = emb[k*C_ + c];
        acc = __fadd_rn(acc, __fmul_rn(v, v));
    }
    g_s[k] = acc;
}

// Batched GEMM (128k x 128n tile per block, K-ascending single-accumulator fmaf chain)
// fused with dist assembly + per-kblock argmin (first-index tie-break)
__global__ __launch_bounds__(256, 2) void k_gemm(const float* __restrict__ emb) {
    int nb = blockIdx.x;            // 0..7
    int kb = blockIdx.y;            // 0..7
    int b  = blockIdx.z;            // 0..31
    int n0 = nb*128, k0 = kb*128;
    __shared__ float Es[32][136];   // Es[i][k]  (transposed for vector loads)
    __shared__ float Zs[32][136];   // Zs[i][n]
    int t  = threadIdx.x;
    int tx = t & 15, ty = t >> 4;

    float acc[8][8];
    #pragma unroll
    for (int r = 0; r < 8; ++r)
        #pragma unroll
        for (int c = 0; c < 8; ++c) acc[r][c] = 0.f;

    for (int it = 0; it < 8; ++it) {
        __syncthreads();
        for (int e = t; e < 4096; e += 256) {
            int kk = e >> 5, ii = e & 31;
            Es[ii][kk] = emb[(k0+kk)*256 + it*32 + ii];
        }
        for (int e = t; e < 4096; e += 256) {
            int ii = e >> 7, nn = e & 127;
            Zs[ii][nn] = g_zz[b][it*32 + ii][n0 + nn];
        }
        __syncthreads();
        #pragma unroll
        for (int ii = 0; ii < 32; ++ii) {
            float4 a0 = *(const float4*)&Es[ii][ty*8];
            float4 a1 = *(const float4*)&Es[ii][ty*8+4];
            float4 b0 = *(const float4*)&Zs[ii][tx*8];
            float4 b1 = *(const float4*)&Zs[ii][tx*8+4];
            float av[8] = {a0.x,a0.y,a0.z,a0.w,a1.x,a1.y,a1.z,a1.w};
            float bv[8] = {b0.x,b0.y,b0.z,b0.w,b1.x,b1.y,b1.z,b1.w};
            #pragma unroll
            for (int r = 0; r < 8; ++r)
                #pragma unroll
                for (int c = 0; c < 8; ++c)
                    acc[r][c] = fmaf(av[r], bv[c], acc[r][c]);
        }
    }

    // dist = fl(fl(s_k + t_n) - 2*dot), local argmin over this thread's 8 k (ascending, strict <)
    float sv[8], tv[8];
    #pragma unroll
    for (int r = 0; r < 8; ++r) sv[r] = g_s[k0 + ty*8 + r];
    #pragma unroll
    for (int c = 0; c < 8; ++c) tv[c] = g_t[b*1024 + n0 + tx*8 + c];

    float mv[8]; int mi[8];
    #pragma unroll
    for (int c = 0; c < 8; ++c) {
        float d0 = __fsub_rn(__fadd_rn(sv[0], tv[c]), __fmul_rn(2.0f, acc[0][c]));
        mv[c] = d0; mi[c] = k0 + ty*8;
        #pragma unroll
        for (int r = 1; r < 8; ++r) {
            float d = __fsub_rn(__fadd_rn(sv[r], tv[c]), __fmul_rn(2.0f, acc[r][c]));
            if (d < mv[c]) { mv[c] = d; mi[c] = k0 + ty*8 + r; }
        }
    }

    // cross-ty reduction (lex on (d, k) -> global first-min semantics)
    __syncthreads();
    float* red  = (float*)Es;   // 16*128 floats fits
    int*   ridx = (int*)Zs;
    #pragma unroll
    for (int c = 0; c < 8; ++c) {
        red [ty*128 + tx*8 + c] = mv[c];
        ridx[ty*128 + tx*8 + c] = mi[c];
    }
    __syncthreads();
    if (t < 128) {
        float best = red[t]; int bi = ridx[t];
        for (int y = 1; y < 16; ++y) {
            float d = red[y*128 + t]; int ix = ridx[y*128 + t];
            if (d < best || (d == best && ix < bi)) { best = d; bi = ix; }
        }
        int gn = b*1024 + n0 + t;
        g_pmin[gn*8 + kb] = best;
        g_pidx[gn*8 + kb] = bi;
    }
}

__global__ __launch_bounds__(256) void k_combine(float* __restrict__ out, int out_size) {
    int gn = blockIdx.x*blockDim.x + threadIdx.x;
    if (gn >= NPOS) return;
    float best = g_pmin[gn*8]; int bi = g_pidx[gn*8];
    for (int kb = 1; kb < 8; ++kb) {
        float d = g_pmin[gn*8 + kb]; int ix = g_pidx[gn*8 + kb];
        if (d < best || (d == best && ix < bi)) { best = d; bi = ix; }
    }
    g_idx[gn] = bi;
    if (out_size >= ZELEMS + NPOS)      out[ZELEMS + gn] = (float)bi;
    else if (out_size == NPOS)          out[gn]          = (float)bi;
}

// out[b,c,h,w] = fl(z_p + fl(z_q - z_p))  (straight-through, replicated rounding)
// + loss accumulation of fl(fl(diff)^2) in double
__global__ __launch_bounds__(256) void k_writeout(const float* __restrict__ z,
                                                  const float* __restrict__ emb,
                                                  float* __restrict__ out, int out_size) {
    int o = blockIdx.x*256 + threadIdx.x;
    double local = 0.0;
    if (o < ZELEMS) {
        int w = o & 31, h = (o >> 5) & 31, c = (o >> 10) & 255, b = o >> 18;
        int n = h*32 + w;
        int kidx = g_idx[b*1024 + n];
        float zq = emb[kidx*256 + c];
        float zp = z[o];
        float diff = __fsub_rn(zq, zp);
        if (out_size >= ZELEMS) out[o] = __fadd_rn(zp, diff);
        float sq = __fmul_rn(diff, diff);
        local = (double)sq;
    }
    __shared__ double sd[256];
    sd[threadIdx.x] = local;
    __syncthreads();
    for (int s = 128; s > 0; s >>= 1) {
        if (threadIdx.x < s) sd[threadIdx.x] += sd[threadIdx.x + s];
        __syncthreads();
    }
    if (threadIdx.x == 0) atomicAdd(&g_lacc, sd[0]);
}

__global__ void k_finalize(float* __restrict__ out, int out_size) {
    float m = (float)(g_lacc / (double)ZELEMS);
    float loss = __fadd_rn(m, __fmul_rn(0.25f, m));
    if (out_size >= ZELEMS + NPOS + 1)  out[ZELEMS + NPOS] = loss;
    else if (out_size == ZELEMS + 1)    out[ZELEMS]        = loss;
    else if (out_size == 1)             out[0]             = loss;
}

extern "C" void kernel_launch(void* const* d_in, const int* in_sizes, int n_in,
                              void* d_out, int out_size) {
    const float* z   = (const float*)d_in[0];
    const float* emb = (const float*)d_in[1];
    if (n_in >= 2 && in_sizes[0] == K_*C_ && in_sizes[1] == ZELEMS) {
        z = (const float*)d_in[1]; emb = (const float*)d_in[0];
    }
    float* out = (float*)d_out;

    k_init<<<1, 1>>>();
    k_transpose<<<dim3(4, 32, 32), 256>>>(z);
    k_tn<<<NPOS/256, 256>>>();
    k_sk<<<K_/256, 256>>>(emb);
    k_gemm<<<dim3(8, 8, 32), 256>>>(emb);
    k_combine<<<NPOS/256, 256>>>(out, out_size);
    k_writeout<<<ZELEMS/256, 256>>>(z, emb, out, out_size);
    k_finalize<<<1, 1>>>(out, out_size);
}